// round 11
// baseline (speedup 1.0000x reference)
#include <cuda_runtime.h>
#include <cuda_bf16.h>
#include <cstdint>

// GraphSage_89781996355909 — exact algebraic collapse.
//
// The reference's final op is jax.nn.softmax(x @ W5 + b5, axis=-1) with
// last-axis dimension 1 (W5: [8,1]). Softmax over a single element is
// identically 1.0 for any finite logit, and all upstream values are finite
// (Gaussian inputs through gather/GEMM/ReLU/l2-normalize — no overflow path),
// so the entire 34-GFLOP forward pass reduces to out = ones(512) for ALL
// inputs, not just this seed.
//
// FINAL KERNEL — converged optimum, 5x-reproduced on the stable metric
// (ncu kernel duration):
//   this config:     2.912 / 2.944 / 2.912 / 2.944 / 2.976 us (R3/R5/R7/R8/R9)
//   1-warp unrolled: 3.136 us (R4)   unpredicated: 3.168 us (R6)
//   2-CTA scalar:    4.128 us (R1)
// Single CTA, 128 threads, one predicated STG.128 per thread (128 float4 =
// 512 floats); four warps issue across all four SMSPs in parallel. The
// kernel runs at empty-kernel launch+drain latency (DRAM/L2/issue ~0%);
// residual total-time variance (4.58-5.54us for this identical binary) is
// harness graph-replay noise, not kernel-controllable.
// Scalar fallback kept for any other out_size/alignment.

__global__ void GraphSage_89781996355909_fill4(float4* __restrict__ out4, int n4) {
    int i = threadIdx.x + blockIdx.x * blockDim.x;
    if (i < n4) out4[i] = make_float4(1.0f, 1.0f, 1.0f, 1.0f);
}

__global__ void GraphSage_89781996355909_fill1(float* __restrict__ out, int n) {
    int i = threadIdx.x + blockIdx.x * blockDim.x;
    if (i < n) out[i] = 1.0f;
}

extern "C" void kernel_launch(void* const* d_in, const int* in_sizes, int n_in,
                              void* d_out, int out_size) {
    (void)d_in; (void)in_sizes; (void)n_in;
    if ((out_size & 3) == 0 && (((unsigned long long)d_out) & 15ull) == 0) {
        int n4 = out_size >> 2;              // 512 -> 128
        int threads = (n4 < 128) ? (n4 > 0 ? n4 : 1) : 128;
        int blocks = (n4 + threads - 1) / threads;
        if (blocks < 1) blocks = 1;
        GraphSage_89781996355909_fill4<<<blocks, threads>>>((float4*)d_out, n4);
    } else {
        int threads = 256;
        int blocks = (out_size + threads - 1) / threads;
        if (blocks < 1) blocks = 1;
        GraphSage_89781996355909_fill1<<<blocks, threads>>>((float*)d_out, out_size);
    }
}

// round 12
// speedup vs baseline: 1.0556x; 1.0556x over previous
#include <cuda_runtime.h>
#include <cuda_bf16.h>
#include <cstdint>

// GraphSage_89781996355909 — exact algebraic collapse.
//
// The reference's final op is jax.nn.softmax(x @ W5 + b5, axis=-1) with
// last-axis dimension 1 (W5: [8,1]). Softmax over a single element is
// identically 1.0 for any finite logit, and all upstream values are finite
// (Gaussian inputs through gather/GEMM/ReLU/l2-normalize — no overflow path),
// so the entire 34-GFLOP forward pass reduces to out = ones(512) for ALL
// inputs, not just this seed.
//
// FINAL KERNEL — converged optimum, 6x-reproduced:
//   this config kernel dur: 2.912/2.944/2.912/2.944/2.976/3.392 us
//                           (R3/R5/R7/R8/R9/R11 — identical binary; spread
//                            is clock/replay noise at the empty-kernel floor)
//   1-warp unrolled: 3.136 us (R4)   unpredicated: 3.168 us (R6)
//   2-CTA scalar:    4.128 us (R1)
// Single CTA, 128 threads, one predicated STG.128 per thread (128 float4 =
// 512 floats); four warps issue across all four SMSPs in parallel. All ncu
// pipe/memory counters ~0%: the kernel runs at launch+drain latency. Total
// dur_us variance (4.58-5.54us for this identical binary) is harness
// graph-replay noise, not kernel-controllable.
// Scalar fallback kept for any other out_size/alignment.

__global__ void GraphSage_89781996355909_fill4(float4* __restrict__ out4, int n4) {
    int i = threadIdx.x + blockIdx.x * blockDim.x;
    if (i < n4) out4[i] = make_float4(1.0f, 1.0f, 1.0f, 1.0f);
}

__global__ void GraphSage_89781996355909_fill1(float* __restrict__ out, int n) {
    int i = threadIdx.x + blockIdx.x * blockDim.x;
    if (i < n) out[i] = 1.0f;
}

extern "C" void kernel_launch(void* const* d_in, const int* in_sizes, int n_in,
                              void* d_out, int out_size) {
    (void)d_in; (void)in_sizes; (void)n_in;
    if ((out_size & 3) == 0 && (((unsigned long long)d_out) & 15ull) == 0) {
        int n4 = out_size >> 2;              // 512 -> 128
        int threads = (n4 < 128) ? (n4 > 0 ? n4 : 1) : 128;
        int blocks = (n4 + threads - 1) / threads;
        if (blocks < 1) blocks = 1;
        GraphSage_89781996355909_fill4<<<blocks, threads>>>((float4*)d_out, n4);
    } else {
        int threads = 256;
        int blocks = (out_size + threads - 1) / threads;
        if (blocks < 1) blocks = 1;
        GraphSage_89781996355909_fill1<<<blocks, threads>>>((float*)d_out, out_size);
    }
}

// round 13
// speedup vs baseline: 1.0629x; 1.0070x over previous
#include <cuda_runtime.h>
#include <cuda_bf16.h>
#include <cstdint>

// GraphSage_89781996355909 — exact algebraic collapse.
//
// The reference's final op is jax.nn.softmax(x @ W5 + b5, axis=-1) with
// last-axis dimension 1 (W5: [8,1]). Softmax over a single element is
// identically 1.0 for any finite logit, and all upstream values are finite
// (Gaussian inputs through gather/GEMM/ReLU/l2-normalize — no overflow path),
// so the entire 34-GFLOP forward pass reduces to out = ones(512) for ALL
// inputs, not just this seed.
//
// FINAL KERNEL — converged optimum, 7x-reproduced:
//   this config kernel dur: 2.912/2.944/2.912/2.944/2.976/3.392/3.072 us
//                           (R3/R5/R7/R8/R9/R11/R12 — identical binary;
//                            spread is clock/replay noise at the floor)
//   1-warp unrolled: 3.136 us (R4)   unpredicated: 3.168 us (R6)
//   2-CTA scalar:    4.128 us (R1)
// Single CTA, 128 threads, one predicated STG.128 per thread (128 float4 =
// 512 floats); four warps issue across all four SMSPs in parallel. All ncu
// pipe/memory counters ~0%: the kernel runs at launch+drain latency. Total
// dur_us variance (4.58-5.54us for this identical binary) is harness
// graph-replay noise, not kernel-controllable.
// Scalar fallback kept for any other out_size/alignment.

__global__ void GraphSage_89781996355909_fill4(float4* __restrict__ out4, int n4) {
    int i = threadIdx.x + blockIdx.x * blockDim.x;
    if (i < n4) out4[i] = make_float4(1.0f, 1.0f, 1.0f, 1.0f);
}

__global__ void GraphSage_89781996355909_fill1(float* __restrict__ out, int n) {
    int i = threadIdx.x + blockIdx.x * blockDim.x;
    if (i < n) out[i] = 1.0f;
}

extern "C" void kernel_launch(void* const* d_in, const int* in_sizes, int n_in,
                              void* d_out, int out_size) {
    (void)d_in; (void)in_sizes; (void)n_in;
    if ((out_size & 3) == 0 && (((unsigned long long)d_out) & 15ull) == 0) {
        int n4 = out_size >> 2;              // 512 -> 128
        int threads = (n4 < 128) ? (n4 > 0 ? n4 : 1) : 128;
        int blocks = (n4 + threads - 1) / threads;
        if (blocks < 1) blocks = 1;
        GraphSage_89781996355909_fill4<<<blocks, threads>>>((float4*)d_out, n4);
    } else {
        int threads = 256;
        int blocks = (out_size + threads - 1) / threads;
        if (blocks < 1) blocks = 1;
        GraphSage_89781996355909_fill1<<<blocks, threads>>>((float*)d_out, out_size);
    }
}